// round 1
// baseline (speedup 1.0000x reference)
#include <cuda_runtime.h>

#define NB    32    // batch (indices)
#define PMODES 4    // probe modes
#define NSL    8    // slices
#define NN   256    // ROI
#define LINES  4    // FFT lines per block
#define TPL  128    // threads per line (radix-2: N/2)

// Scratch: psi[b][pm][y][x], state between kernels is Fr(psi) (row-FFT'd)
__device__ float2 g_psi[NB * PMODES * NN * NN];

__device__ __forceinline__ float2 cmul(float2 a, float2 b) {
    return make_float2(a.x * b.x - a.y * b.y, a.x * b.y + a.y * b.x);
}

__device__ __forceinline__ void init_tw(float2* tw) {
    int flat = threadIdx.y * TPL + threadIdx.x;
    if (flat < 128) {
        float s, c;
        sincospif(-(float)flat / 128.0f, &s, &c);  // W_256^k = exp(-2*pi*i*k/256)
        tw[flat] = make_float2(c, s);
    }
}

// 256-point Stockham radix-2 FFT on one smem line, 128 threads (t in [0,128)).
// Input in X, output lands back in X after 8 stages. Block-wide syncs between
// stages (all lines in the block run in lockstep). INV = conjugate twiddles
// (unnormalized inverse; scaling folded into pointwise steps by callers).
template <bool INV>
__device__ __forceinline__ void fft256(float2* X, float2* Y, int t, const float2* tw) {
    float2* x = X;
    float2* y = Y;
#pragma unroll
    for (int stage = 0; stage < 8; stage++) {
        int s = 1 << stage;
        int m = 128 >> stage;
        int p = t >> stage;
        int q = t & (s - 1);
        float2 a = x[q + s * p];
        float2 b = x[q + s * (p + m)];
        float2 w = tw[p << stage];     // W_256^{p * 256/n}, n = 256>>stage
        if (INV) w.y = -w.y;
        y[q + 2 * s * p]     = make_float2(a.x + b.x, a.y + b.y);
        float2 d = make_float2(a.x - b.x, a.y - b.y);
        y[q + 2 * s * p + s] = cmul(d, w);
        __syncthreads();
        float2* tmp = x; x = y; y = tmp;
    }
}

// ---------------------------------------------------------------------------
// k_init: psi = to_complex(bilinear_translate(probe)) * to_complex(obj slice 0)
//         then forward row FFT. One block = LINES rows of one (b, pm) image.
// ---------------------------------------------------------------------------
__global__ void k_init(const float* __restrict__ obj, const float* __restrict__ probe,
                       const float* __restrict__ shifts, const int* __restrict__ crop,
                       const int* __restrict__ idxs) {
    __shared__ float2 sA[LINES][NN + 2];
    __shared__ float2 sB[LINES][NN + 2];
    __shared__ float2 s_tw[128];
    init_tw(s_tw);

    int t = threadIdx.x, ly = threadIdx.y;
    int img = blockIdx.y;            // 0..127
    int b = img >> 2, pm = img & 3;
    int r = blockIdx.x * LINES + ly; // row

    int id = idxs[b];
    float tH = shifts[2 * id + 0];
    float tW = shifts[2 * id + 1];
    int p0 = crop[2 * id + 0];
    int p1 = crop[2 * id + 1];

    float ys = (float)r - tH;
    float y0f = floorf(ys);
    float wy = ys - y0f;
    int y0 = (int)y0f;

#pragma unroll
    for (int k = 0; k < 2; k++) {
        int c = t + k * TPL;
        float xs = (float)c - tW;
        float x0f = floorf(xs);
        float wx = xs - x0f;
        int x0 = (int)x0f;

        float amp = 0.f, ph = 0.f;
#pragma unroll
        for (int dy = 0; dy < 2; dy++) {
            int yy = y0 + dy;
            float wyt = dy ? wy : (1.f - wy);
            if (yy >= 0 && yy < NN) {
#pragma unroll
                for (int dx = 0; dx < 2; dx++) {
                    int xx = x0 + dx;
                    float w = wyt * (dx ? wx : (1.f - wx));
                    if (xx >= 0 && xx < NN) {
                        float2 v = *(const float2*)(probe + ((size_t)(pm * NN + yy) * NN + xx) * 2);
                        amp = fmaf(w, v.x, amp);
                        ph  = fmaf(w, v.y, ph);
                    }
                }
            }
        }
        float sn, cs;
        __sincosf(ph, &sn, &cs);
        float2 pc = make_float2(amp * cs, amp * sn);

        // obj slice 0 patch pixel
        float2 o = *(const float2*)(obj + (((size_t)(p0 + r)) * 1024 + (p1 + c)) * 2);
        float so, co;
        __sincosf(o.y, &so, &co);
        float2 oc = make_float2(o.x * co, o.x * so);

        sA[ly][c] = cmul(pc, oc);
    }
    __syncthreads();

    fft256<false>(&sA[ly][0], &sB[ly][0], t, s_tw);

    float2* dst = g_psi + (size_t)img * NN * NN + (size_t)r * NN;
    dst[t]       = sA[ly][t];
    dst[t + TPL] = sA[ly][t + TPL];
}

// ---------------------------------------------------------------------------
// k_col: per column: Fc -> * (H/256) -> Fc^{-1}. One block = LINES columns of
// one image. Columns staged through smem with coalesced 32B-chunk access.
// ---------------------------------------------------------------------------
__global__ void k_col(const float* __restrict__ Hr, const float* __restrict__ Hi) {
    __shared__ float2 sA[LINES][NN + 2];
    __shared__ float2 sB[LINES][NN + 2];
    __shared__ float2 sH[LINES][NN + 2];
    __shared__ float2 s_tw[128];
    init_tw(s_tw);

    int t = threadIdx.x, ly = threadIdx.y;
    int img = blockIdx.y;
    int cb = blockIdx.x * LINES;
    int flat = ly * TPL + t;
    const float inv = 1.0f / 256.0f;
    float2* psi = g_psi + (size_t)img * NN * NN;

    for (int e = flat; e < NN * LINES; e += TPL * LINES) {
        int row = e >> 2;      // LINES == 4
        int col = e & 3;
        sA[col][row] = psi[row * NN + cb + col];
        sH[col][row] = make_float2(Hr[row * NN + cb + col] * inv,
                                   Hi[row * NN + cb + col] * inv);
    }
    __syncthreads();

    fft256<false>(&sA[ly][0], &sB[ly][0], t, s_tw);

#pragma unroll
    for (int k = 0; k < 2; k++) {
        int r = t + k * TPL;
        sA[ly][r] = cmul(sA[ly][r], sH[ly][r]);
    }
    __syncthreads();

    fft256<true>(&sA[ly][0], &sB[ly][0], t, s_tw);

    for (int e = flat; e < NN * LINES; e += TPL * LINES) {
        int row = e >> 2;
        int col = e & 3;
        psi[row * NN + cb + col] = sA[col][row];
    }
}

// ---------------------------------------------------------------------------
// k_row: per row: Fr^{-1}/256 -> * obj_z -> Fr. One block = LINES rows of one
// BATCH element; loops over the 4 probe modes reusing the obj sincos.
// ---------------------------------------------------------------------------
__global__ void k_row(const float* __restrict__ obj, const int* __restrict__ crop,
                      const int* __restrict__ idxs, int z) {
    __shared__ float2 sA[LINES][NN + 2];
    __shared__ float2 sB[LINES][NN + 2];
    __shared__ float2 sO[LINES][NN + 2];
    __shared__ float2 s_tw[128];
    init_tw(s_tw);

    int t = threadIdx.x, ly = threadIdx.y;
    int b = blockIdx.y;
    int r = blockIdx.x * LINES + ly;

    int id = idxs[b];
    int p0 = crop[2 * id + 0];
    int p1 = crop[2 * id + 1];
    const float inv = 1.0f / 256.0f;

#pragma unroll
    for (int k = 0; k < 2; k++) {
        int c = t + k * TPL;
        float2 o = *(const float2*)(obj + (((size_t)z * 1024 + p0 + r) * 1024 + (p1 + c)) * 2);
        float so, co;
        __sincosf(o.y, &so, &co);
        sO[ly][c] = make_float2(o.x * co * inv, o.x * so * inv);
    }
    __syncthreads();

    for (int pm = 0; pm < PMODES; pm++) {
        float2* psi = g_psi + ((size_t)(b * PMODES + pm) * NN + r) * NN;
        sA[ly][t]       = psi[t];
        sA[ly][t + TPL] = psi[t + TPL];
        __syncthreads();

        fft256<true>(&sA[ly][0], &sB[ly][0], t, s_tw);

#pragma unroll
        for (int k = 0; k < 2; k++) {
            int c = t + k * TPL;
            sA[ly][c] = cmul(sA[ly][c], sO[ly][c]);
        }
        __syncthreads();

        fft256<false>(&sA[ly][0], &sB[ly][0], t, s_tw);

        psi[t]       = sA[ly][t];
        psi[t + TPL] = sA[ly][t + TPL];
        __syncthreads();  // protect sA before next pm's load
    }
}

// ---------------------------------------------------------------------------
// k_final: per column: Fc, accumulate |.|^2 over 4 probe modes, write dp.
// One block = LINES columns of one batch element.
// ---------------------------------------------------------------------------
__global__ void k_final(float* __restrict__ out) {
    __shared__ float2 sA[LINES][NN + 2];
    __shared__ float2 sB[LINES][NN + 2];
    __shared__ float  sAcc[LINES][NN + 1];
    __shared__ float2 s_tw[128];
    init_tw(s_tw);

    int t = threadIdx.x, ly = threadIdx.y;
    int b = blockIdx.y;
    int cb = blockIdx.x * LINES;
    int flat = ly * TPL + t;

    float acc0 = 0.f, acc1 = 0.f;

    for (int pm = 0; pm < PMODES; pm++) {
        float2* psi = g_psi + (size_t)(b * PMODES + pm) * NN * NN;
        for (int e = flat; e < NN * LINES; e += TPL * LINES) {
            int row = e >> 2;
            int col = e & 3;
            sA[col][row] = psi[row * NN + cb + col];
        }
        __syncthreads();

        fft256<false>(&sA[ly][0], &sB[ly][0], t, s_tw);

        float2 v0 = sA[ly][t];
        float2 v1 = sA[ly][t + TPL];
        acc0 = fmaf(v0.x, v0.x, fmaf(v0.y, v0.y, acc0));
        acc1 = fmaf(v1.x, v1.x, fmaf(v1.y, v1.y, acc1));
        __syncthreads();  // protect sA before next pm's load
    }

    sAcc[ly][t]       = acc0;
    sAcc[ly][t + TPL] = acc1;
    __syncthreads();

    for (int e = flat; e < NN * LINES; e += TPL * LINES) {
        int row = e >> 2;
        int col = e & 3;
        out[(size_t)b * NN * NN + row * NN + cb + col] = sAcc[col][row];
    }
}

// ---------------------------------------------------------------------------
extern "C" void kernel_launch(void* const* d_in, const int* in_sizes, int n_in,
                              void* d_out, int out_size) {
    const float* obj    = (const float*)d_in[0];  // (1,8,1024,1024,2)
    const float* probe  = (const float*)d_in[1];  // (4,256,256,2)
    const float* shifts = (const float*)d_in[2];  // (1024,2)
    const int*   crop   = (const int*)d_in[3];    // (1024,2)
    const float* Hr     = (const float*)d_in[4];  // (256,256)
    const float* Hi     = (const float*)d_in[5];  // (256,256)
    const int*   idxs   = (const int*)d_in[6];    // (32,)
    float* out = (float*)d_out;                   // (32,256,256)

    dim3 blk(TPL, LINES);
    k_init<<<dim3(NN / LINES, NB * PMODES), blk>>>(obj, probe, shifts, crop, idxs);
    for (int z = 0; z < NSL - 1; z++) {
        k_col<<<dim3(NN / LINES, NB * PMODES), blk>>>(Hr, Hi);
        k_row<<<dim3(NN / LINES, NB), blk>>>(obj, crop, idxs, z + 1);
    }
    k_final<<<dim3(NN / LINES, NB), blk>>>(out);
}

// round 2
// speedup vs baseline: 2.3534x; 2.3534x over previous
#include <cuda_runtime.h>

#define NB   32    // batch
#define PM    4    // probe modes
#define NSL   8    // slices
#define NN  256    // ROI
#define LNS  16    // FFT lines per block
// block = (16 threads per line) x (16 lines) = 256 threads

// psi[b][pm][y][x]; state between kernels is Fr(psi) (row-FFT'd, natural order)
__device__ float2 g_psi[NB * PM * NN * NN];
// Ht[col][row] = (H[row][col]) / 256  (transposed for coalesced column access)
__device__ float2 g_Ht[NN * NN];

__device__ __forceinline__ float2 cmul(float2 a, float2 b) {
    return make_float2(fmaf(a.x, b.x, -a.y * b.y), fmaf(a.x, b.y, a.y * b.x));
}

// W16^m = exp(-2*pi*i*m/16), m = 0..9 (only k1*n2 in {0..9} used)
__constant__ float2 W16C[10] = {
    { 1.0f,          0.0f        },
    { 0.92387953f,  -0.38268343f },
    { 0.70710678f,  -0.70710678f },
    { 0.38268343f,  -0.92387953f },
    { 0.0f,         -1.0f        },
    {-0.38268343f,  -0.92387953f },
    {-0.70710678f,  -0.70710678f },
    {-0.92387953f,  -0.38268343f },
    {-1.0f,          0.0f        },
    {-0.92387953f,   0.38268343f },
};

template <bool INV>
__device__ __forceinline__ void bf4(float2& a, float2& b, float2& c, float2& d) {
    float2 t0 = make_float2(a.x + c.x, a.y + c.y);
    float2 t1 = make_float2(a.x - c.x, a.y - c.y);
    float2 t2 = make_float2(b.x + d.x, b.y + d.y);
    float2 t3 = make_float2(b.x - d.x, b.y - d.y);
    a = make_float2(t0.x + t2.x, t0.y + t2.y);
    c = make_float2(t0.x - t2.x, t0.y - t2.y);
    if (!INV) {
        b = make_float2(t1.x + t3.y, t1.y - t3.x);  // t1 - i*t3
        d = make_float2(t1.x - t3.y, t1.y + t3.x);  // t1 + i*t3
    } else {
        b = make_float2(t1.x - t3.y, t1.y + t3.x);
        d = make_float2(t1.x + t3.y, t1.y - t3.x);
    }
}

// 16-point DFT fully in registers. v is clobbered; out gets natural-order result.
template <bool INV>
__device__ __forceinline__ void fft16(float2* v, float2* out) {
#pragma unroll
    for (int n2 = 0; n2 < 4; n2++)
        bf4<INV>(v[n2], v[4 + n2], v[8 + n2], v[12 + n2]);
#pragma unroll
    for (int k1 = 1; k1 < 4; k1++)
#pragma unroll
        for (int n2 = 1; n2 < 4; n2++) {
            float2 w = W16C[k1 * n2];
            if (INV) w.y = -w.y;
            v[4 * k1 + n2] = cmul(v[4 * k1 + n2], w);
        }
#pragma unroll
    for (int k1 = 0; k1 < 4; k1++)
        bf4<INV>(v[4 * k1 + 0], v[4 * k1 + 1], v[4 * k1 + 2], v[4 * k1 + 3]);
    // v[4*k1 + k2] = X[k1 + 4*k2]  -> permute to natural order
#pragma unroll
    for (int k1 = 0; k1 < 4; k1++)
#pragma unroll
        for (int k2 = 0; k2 < 4; k2++)
            out[k1 + 4 * k2] = v[4 * k1 + k2];
}

// 256-point FFT, 16 threads per line. Input/output: reg[s] = element (16*s + t).
// tr: per-line 16x17 float2 transpose buffer. wfwd = W256^t (forward sign).
// Two block-wide syncs inside (uniform across all lines).
template <bool INV>
__device__ __forceinline__ void fft256(float2 reg[16], int t, float2* tr, float2 wfwd) {
    float2 A[16];
    fft16<INV>(reg, A);
    float2 w = wfwd;
    if (INV) w.y = -w.y;
    float2 wk = w;
#pragma unroll
    for (int k1 = 1; k1 < 16; k1++) {
        A[k1] = cmul(A[k1], wk);
        wk = cmul(wk, w);
    }
#pragma unroll
    for (int k1 = 0; k1 < 16; k1++) tr[k1 * 17 + t] = A[k1];
    __syncthreads();
    float2 B[16];
#pragma unroll
    for (int n2 = 0; n2 < 16; n2++) B[n2] = tr[t * 17 + n2];
    __syncthreads();
    fft16<INV>(B, reg);  // reg[k2] = X[16*k2 + t]
}

__device__ __forceinline__ float2 w256_fwd(int t) {
    float s, c;
    sincospif(-(float)t * (1.0f / 128.0f), &s, &c);
    return make_float2(c, s);
}

// ---------------------------------------------------------------------------
// k_prep: Ht[col][row] = H[row][col] / 256
// ---------------------------------------------------------------------------
__global__ void k_prep(const float* __restrict__ Hr, const float* __restrict__ Hi) {
    int i = blockIdx.x * blockDim.x + threadIdx.x;
    int row = i >> 8, col = i & 255;
    g_Ht[(size_t)col * NN + row] =
        make_float2(Hr[i] * (1.0f / 256.0f), Hi[i] * (1.0f / 256.0f));
}

// ---------------------------------------------------------------------------
// k_init: psi = probe_translated * obj0, then forward row FFT.
// One line = one row of one (b, pm) image.
// ---------------------------------------------------------------------------
__global__ __launch_bounds__(256) void k_init(
    const float* __restrict__ obj, const float* __restrict__ probe,
    const float* __restrict__ shifts, const int* __restrict__ crop,
    const int* __restrict__ idxs) {
    __shared__ float2 buf[4352];
    int t = threadIdx.x, ly = threadIdx.y;
    int img = blockIdx.y;
    int b = img >> 2, pm = img & 3;
    int r = blockIdx.x * LNS + ly;

    int id = idxs[b];
    float tH = shifts[2 * id + 0];
    float tW = shifts[2 * id + 1];
    int p0 = crop[2 * id + 0];
    int p1 = crop[2 * id + 1];

    float ys = (float)r - tH;
    float y0f = floorf(ys);
    float wy = ys - y0f;
    int y0 = (int)y0f;

    float2 reg[16];
#pragma unroll
    for (int j = 0; j < 16; j++) {
        int c = 16 * j + t;
        float xs = (float)c - tW;
        float x0f = floorf(xs);
        float wx = xs - x0f;
        int x0 = (int)x0f;

        float amp = 0.f, ph = 0.f;
#pragma unroll
        for (int dy = 0; dy < 2; dy++) {
            int yy = y0 + dy;
            float wyt = dy ? wy : (1.f - wy);
            if (yy >= 0 && yy < NN) {
#pragma unroll
                for (int dx = 0; dx < 2; dx++) {
                    int xx = x0 + dx;
                    float w = wyt * (dx ? wx : (1.f - wx));
                    if (xx >= 0 && xx < NN) {
                        float2 v = *(const float2*)(probe +
                            ((size_t)(pm * NN + yy) * NN + xx) * 2);
                        amp = fmaf(w, v.x, amp);
                        ph  = fmaf(w, v.y, ph);
                    }
                }
            }
        }
        float sn, cs;
        __sincosf(ph, &sn, &cs);
        float2 pc = make_float2(amp * cs, amp * sn);

        float2 o = *(const float2*)(obj + (((size_t)(p0 + r)) * 1024 + (p1 + c)) * 2);
        float so, co;
        __sincosf(o.y, &so, &co);
        reg[j] = cmul(pc, make_float2(o.x * co, o.x * so));
    }

    float2 wf = w256_fwd(t);
    fft256<false>(reg, t, buf + ly * 272, wf);

    float2* dst = g_psi + ((size_t)img * NN + r) * NN;
#pragma unroll
    for (int k = 0; k < 16; k++) dst[16 * k + t] = reg[k];
}

// ---------------------------------------------------------------------------
// k_col: per column: Fc -> * (H/256) -> Fc^{-1}. One line = one column.
// Global access staged through smem (coalesced 128B segments).
// ---------------------------------------------------------------------------
__global__ __launch_bounds__(256) void k_col() {
    __shared__ float2 buf[4352];
    int t = threadIdx.x, ly = threadIdx.y;
    int img = blockIdx.y;
    int cb = blockIdx.x * LNS;
    float2* psi = g_psi + (size_t)img * NN * NN;

#pragma unroll
    for (int it = 0; it < 16; it++) {
        int row = it * 16 + ly;
        buf[row * 17 + t] = psi[row * NN + cb + t];
    }
    __syncthreads();
    float2 reg[16];
#pragma unroll
    for (int j = 0; j < 16; j++) reg[j] = buf[(16 * j + t) * 17 + ly];
    __syncthreads();

    float2 wf = w256_fwd(t);
    fft256<false>(reg, t, buf + ly * 272, wf);

    const float2* hcol = g_Ht + (size_t)(cb + ly) * NN;
#pragma unroll
    for (int k = 0; k < 16; k++) reg[k] = cmul(reg[k], hcol[16 * k + t]);

    fft256<true>(reg, t, buf + ly * 272, wf);

#pragma unroll
    for (int k = 0; k < 16; k++) buf[(16 * k + t) * 17 + ly] = reg[k];
    __syncthreads();
#pragma unroll
    for (int it = 0; it < 16; it++) {
        int row = it * 16 + ly;
        psi[row * NN + cb + t] = buf[row * 17 + t];
    }
}

// ---------------------------------------------------------------------------
// k_row: per row: Fr^{-1}/256 -> * obj_z -> Fr. One line = one row of one
// batch element; loops over 4 probe modes reusing the obj sincos (registers).
// ---------------------------------------------------------------------------
__global__ __launch_bounds__(256) void k_row(
    const float* __restrict__ obj, const int* __restrict__ crop,
    const int* __restrict__ idxs, int z) {
    __shared__ float2 buf[4352];
    int t = threadIdx.x, ly = threadIdx.y;
    int b = blockIdx.y;
    int r = blockIdx.x * LNS + ly;

    int id = idxs[b];
    int p0 = crop[2 * id + 0];
    int p1 = crop[2 * id + 1];
    const float inv = 1.0f / 256.0f;

    float2 oc[16];
#pragma unroll
    for (int j = 0; j < 16; j++) {
        int c = 16 * j + t;
        float2 o = *(const float2*)(obj +
            (((size_t)z * 1024 + p0 + r) * 1024 + (p1 + c)) * 2);
        float so, co;
        __sincosf(o.y, &so, &co);
        oc[j] = make_float2(o.x * co * inv, o.x * so * inv);
    }

    float2 wf = w256_fwd(t);

    for (int pm = 0; pm < PM; pm++) {
        float2* psi = g_psi + ((size_t)(b * PM + pm) * NN + r) * NN;
        float2 reg[16];
#pragma unroll
        for (int k = 0; k < 16; k++) reg[k] = psi[16 * k + t];

        fft256<true>(reg, t, buf + ly * 272, wf);
#pragma unroll
        for (int j = 0; j < 16; j++) reg[j] = cmul(reg[j], oc[j]);
        fft256<false>(reg, t, buf + ly * 272, wf);

#pragma unroll
        for (int k = 0; k < 16; k++) psi[16 * k + t] = reg[k];
    }
}

// ---------------------------------------------------------------------------
// k_final: per column: Fc, accumulate |.|^2 over 4 probe modes, write dp.
// ---------------------------------------------------------------------------
__global__ __launch_bounds__(256) void k_final(float* __restrict__ out) {
    __shared__ float2 buf[4352];
    int t = threadIdx.x, ly = threadIdx.y;
    int b = blockIdx.y;
    int cb = blockIdx.x * LNS;

    float2 wf = w256_fwd(t);
    float acc[16];
#pragma unroll
    for (int k = 0; k < 16; k++) acc[k] = 0.f;

    for (int pm = 0; pm < PM; pm++) {
        float2* psi = g_psi + (size_t)(b * PM + pm) * NN * NN;
#pragma unroll
        for (int it = 0; it < 16; it++) {
            int row = it * 16 + ly;
            buf[row * 17 + t] = psi[row * NN + cb + t];
        }
        __syncthreads();
        float2 reg[16];
#pragma unroll
        for (int j = 0; j < 16; j++) reg[j] = buf[(16 * j + t) * 17 + ly];
        __syncthreads();

        fft256<false>(reg, t, buf + ly * 272, wf);
#pragma unroll
        for (int k = 0; k < 16; k++)
            acc[k] = fmaf(reg[k].x, reg[k].x, fmaf(reg[k].y, reg[k].y, acc[k]));
    }

    float* bf = (float*)buf;
#pragma unroll
    for (int k = 0; k < 16; k++) bf[(16 * k + t) * 17 + ly] = acc[k];
    __syncthreads();
#pragma unroll
    for (int it = 0; it < 16; it++) {
        int row = it * 16 + ly;
        out[(size_t)b * NN * NN + row * NN + cb + t] = bf[row * 17 + t];
    }
}

// ---------------------------------------------------------------------------
extern "C" void kernel_launch(void* const* d_in, const int* in_sizes, int n_in,
                              void* d_out, int out_size) {
    const float* obj    = (const float*)d_in[0];  // (1,8,1024,1024,2)
    const float* probe  = (const float*)d_in[1];  // (4,256,256,2)
    const float* shifts = (const float*)d_in[2];  // (1024,2)
    const int*   crop   = (const int*)d_in[3];    // (1024,2)
    const float* Hr     = (const float*)d_in[4];  // (256,256)
    const float* Hi     = (const float*)d_in[5];  // (256,256)
    const int*   idxs   = (const int*)d_in[6];    // (32,)
    float* out = (float*)d_out;                   // (32,256,256)

    dim3 blk(16, LNS);
    k_prep<<<256, 256>>>(Hr, Hi);
    k_init<<<dim3(NN / LNS, NB * PM), blk>>>(obj, probe, shifts, crop, idxs);
    for (int z = 0; z < NSL - 1; z++) {
        k_col<<<dim3(NN / LNS, NB * PM), blk>>>();
        k_row<<<dim3(NN / LNS, NB), blk>>>(obj, crop, idxs, z + 1);
    }
    k_final<<<dim3(NN / LNS, NB), blk>>>(out);
}

// round 4
// speedup vs baseline: 3.4155x; 1.4513x over previous
#include <cuda_runtime.h>

#define NB   32    // batch
#define PM    4    // probe modes
#define NSL   8    // slices
#define NN  256    // ROI
#define LNS  16    // FFT lines per block (k_init/k_col/k_final: 256 thr)
#define LNSR  8    // FFT lines per block for k_row (128 thr)

// psi[b][pm][y][x]; state between kernels is Fr(psi) (row-FFT'd, natural order)
__device__ float2 g_psi[NB * PM * NN * NN];
// Ht[col][row] = (H[row][col]) / 256  (transposed for coalesced column access)
__device__ float2 g_Ht[NN * NN];

__device__ __forceinline__ float2 cmul(float2 a, float2 b) {
    return make_float2(fmaf(a.x, b.x, -a.y * b.y), fmaf(a.x, b.y, a.y * b.x));
}

// W16^m = exp(-2*pi*i*m/16), m = 0..9 (only k1*n2 in {0..9} used)
__constant__ float2 W16C[10] = {
    { 1.0f,          0.0f        },
    { 0.92387953f,  -0.38268343f },
    { 0.70710678f,  -0.70710678f },
    { 0.38268343f,  -0.92387953f },
    { 0.0f,         -1.0f        },
    {-0.38268343f,  -0.92387953f },
    {-0.70710678f,  -0.70710678f },
    {-0.92387953f,  -0.38268343f },
    {-1.0f,          0.0f        },
    {-0.92387953f,   0.38268343f },
};

template <bool INV>
__device__ __forceinline__ void bf4(float2& a, float2& b, float2& c, float2& d) {
    float2 t0 = make_float2(a.x + c.x, a.y + c.y);
    float2 t1 = make_float2(a.x - c.x, a.y - c.y);
    float2 t2 = make_float2(b.x + d.x, b.y + d.y);
    float2 t3 = make_float2(b.x - d.x, b.y - d.y);
    a = make_float2(t0.x + t2.x, t0.y + t2.y);
    c = make_float2(t0.x - t2.x, t0.y - t2.y);
    if (!INV) {
        b = make_float2(t1.x + t3.y, t1.y - t3.x);  // t1 - i*t3
        d = make_float2(t1.x - t3.y, t1.y + t3.x);  // t1 + i*t3
    } else {
        b = make_float2(t1.x - t3.y, t1.y + t3.x);
        d = make_float2(t1.x + t3.y, t1.y - t3.x);
    }
}

// 16-point DFT fully in registers. v is clobbered; out gets natural-order result.
template <bool INV>
__device__ __forceinline__ void fft16(float2* v, float2* out) {
#pragma unroll
    for (int n2 = 0; n2 < 4; n2++)
        bf4<INV>(v[n2], v[4 + n2], v[8 + n2], v[12 + n2]);
#pragma unroll
    for (int k1 = 1; k1 < 4; k1++)
#pragma unroll
        for (int n2 = 1; n2 < 4; n2++) {
            float2 w = W16C[k1 * n2];
            if (INV) w.y = -w.y;
            v[4 * k1 + n2] = cmul(v[4 * k1 + n2], w);
        }
#pragma unroll
    for (int k1 = 0; k1 < 4; k1++)
        bf4<INV>(v[4 * k1 + 0], v[4 * k1 + 1], v[4 * k1 + 2], v[4 * k1 + 3]);
#pragma unroll
    for (int k1 = 0; k1 < 4; k1++)
#pragma unroll
        for (int k2 = 0; k2 < 4; k2++)
            out[k1 + 4 * k2] = v[4 * k1 + k2];
}

// 256-point FFT, 16 threads per line. reg[s] = element (16*s + t).
// tr: per-line 16x17 float2 transpose buffer — touched ONLY by this line's 16
// threads, which live inside one warp, so __syncwarp suffices (no block sync).
template <bool INV>
__device__ __forceinline__ void fft256(float2 reg[16], int t, float2* tr, float2 wfwd) {
    float2 A[16];
    fft16<INV>(reg, A);
    float2 w = wfwd;
    if (INV) w.y = -w.y;
    float2 wk = w;
#pragma unroll
    for (int k1 = 1; k1 < 16; k1++) {
        A[k1] = cmul(A[k1], wk);
        wk = cmul(wk, w);
    }
#pragma unroll
    for (int k1 = 0; k1 < 16; k1++) tr[k1 * 17 + t] = A[k1];
    __syncwarp();
    float2 B[16];
#pragma unroll
    for (int n2 = 0; n2 < 16; n2++) B[n2] = tr[t * 17 + n2];
    __syncwarp();
    fft16<INV>(B, reg);  // reg[k2] = X[16*k2 + t]
}

__device__ __forceinline__ float2 w256_fwd(int t) {
    float s, c;
    sincospif(-(float)t * (1.0f / 128.0f), &s, &c);
    return make_float2(c, s);
}

// ---------------------------------------------------------------------------
__global__ void k_prep(const float* __restrict__ Hr, const float* __restrict__ Hi) {
    int i = blockIdx.x * blockDim.x + threadIdx.x;
    int row = i >> 8, col = i & 255;
    g_Ht[(size_t)col * NN + row] =
        make_float2(Hr[i] * (1.0f / 256.0f), Hi[i] * (1.0f / 256.0f));
}

// ---------------------------------------------------------------------------
// k_init: psi = probe_translated * obj0, then forward row FFT.
// Fully warp-synchronous (all smem is line-local).
// ---------------------------------------------------------------------------
__global__ __launch_bounds__(256, 2) void k_init(
    const float* __restrict__ obj, const float* __restrict__ probe,
    const float* __restrict__ shifts, const int* __restrict__ crop,
    const int* __restrict__ idxs) {
    __shared__ float2 buf[LNS * 272];
    int t = threadIdx.x, ly = threadIdx.y;
    int img = blockIdx.y;
    int b = img >> 2, pm = img & 3;
    int r = blockIdx.x * LNS + ly;

    int id = idxs[b];
    float tH = shifts[2 * id + 0];
    float tW = shifts[2 * id + 1];
    int p0 = crop[2 * id + 0];
    int p1 = crop[2 * id + 1];

    float ys = (float)r - tH;
    float y0f = floorf(ys);
    float wy = ys - y0f;
    int y0 = (int)y0f;

    float2 reg[16];
#pragma unroll
    for (int j = 0; j < 16; j++) {
        int c = 16 * j + t;
        float xs = (float)c - tW;
        float x0f = floorf(xs);
        float wx = xs - x0f;
        int x0 = (int)x0f;

        float amp = 0.f, ph = 0.f;
#pragma unroll
        for (int dy = 0; dy < 2; dy++) {
            int yy = y0 + dy;
            float wyt = dy ? wy : (1.f - wy);
            if (yy >= 0 && yy < NN) {
#pragma unroll
                for (int dx = 0; dx < 2; dx++) {
                    int xx = x0 + dx;
                    float w = wyt * (dx ? wx : (1.f - wx));
                    if (xx >= 0 && xx < NN) {
                        float2 v = *(const float2*)(probe +
                            ((size_t)(pm * NN + yy) * NN + xx) * 2);
                        amp = fmaf(w, v.x, amp);
                        ph  = fmaf(w, v.y, ph);
                    }
                }
            }
        }
        float sn, cs;
        __sincosf(ph, &sn, &cs);
        float2 pc = make_float2(amp * cs, amp * sn);

        float2 o = *(const float2*)(obj + (((size_t)(p0 + r)) * 1024 + (p1 + c)) * 2);
        float so, co;
        __sincosf(o.y, &so, &co);
        reg[j] = cmul(pc, make_float2(o.x * co, o.x * so));
    }

    float2 wf = w256_fwd(t);
    fft256<false>(reg, t, buf + ly * 272, wf);

    float2* dst = g_psi + ((size_t)img * NN + r) * NN;
#pragma unroll
    for (int k = 0; k < 16; k++) dst[16 * k + t] = reg[k];
}

// ---------------------------------------------------------------------------
// k_col: per column: Fc -> * (H/256) -> Fc^{-1}. Cross-line staging transposes
// keep block syncs; FFT internals are warp-synchronous.
// ---------------------------------------------------------------------------
__global__ __launch_bounds__(256, 2) void k_col() {
    __shared__ float2 buf[LNS * 272];
    int t = threadIdx.x, ly = threadIdx.y;
    int img = blockIdx.y;
    int cb = blockIdx.x * LNS;
    float2* psi = g_psi + (size_t)img * NN * NN;

#pragma unroll
    for (int it = 0; it < 16; it++) {
        int row = it * 16 + ly;
        buf[row * 17 + t] = psi[row * NN + cb + t];
    }
    __syncthreads();
    float2 reg[16];
#pragma unroll
    for (int j = 0; j < 16; j++) reg[j] = buf[(16 * j + t) * 17 + ly];
    __syncthreads();

    float2 wf = w256_fwd(t);
    fft256<false>(reg, t, buf + ly * 272, wf);

    const float2* hcol = g_Ht + (size_t)(cb + ly) * NN;
#pragma unroll
    for (int k = 0; k < 16; k++) reg[k] = cmul(reg[k], hcol[16 * k + t]);

    fft256<true>(reg, t, buf + ly * 272, wf);

    __syncthreads();  // fft done everywhere before reusing buf cross-line
#pragma unroll
    for (int k = 0; k < 16; k++) buf[(16 * k + t) * 17 + ly] = reg[k];
    __syncthreads();
#pragma unroll
    for (int it = 0; it < 16; it++) {
        int row = it * 16 + ly;
        psi[row * NN + cb + t] = buf[row * 17 + t];
    }
}

// ---------------------------------------------------------------------------
// k_row: per row: Fr^{-1}/256 -> * obj_z -> Fr. 8 lines / 128 threads per
// block (smem: 17.4KB buf + 16KB obj cache = 33.4KB < 48KB static cap).
// obj factor cached in line-local smem; fully warp-synchronous.
// ---------------------------------------------------------------------------
__global__ __launch_bounds__(128, 4) void k_row(
    const float* __restrict__ obj, const int* __restrict__ crop,
    const int* __restrict__ idxs, int z) {
    __shared__ float2 buf[LNSR * 272];
    __shared__ float2 sOC[LNSR * 256];
    int t = threadIdx.x, ly = threadIdx.y;
    int b = blockIdx.y;
    int r = blockIdx.x * LNSR + ly;

    int id = idxs[b];
    int p0 = crop[2 * id + 0];
    int p1 = crop[2 * id + 1];
    const float inv = 1.0f / 256.0f;

    float2* oc = sOC + ly * 256;
#pragma unroll
    for (int j = 0; j < 16; j++) {
        int c = 16 * j + t;
        float2 o = *(const float2*)(obj +
            (((size_t)z * 1024 + p0 + r) * 1024 + (p1 + c)) * 2);
        float so, co;
        __sincosf(o.y, &so, &co);
        oc[c] = make_float2(o.x * co * inv, o.x * so * inv);
    }
    __syncwarp();

    float2 wf = w256_fwd(t);

    for (int pm = 0; pm < PM; pm++) {
        float2* psi = g_psi + ((size_t)(b * PM + pm) * NN + r) * NN;
        float2 reg[16];
#pragma unroll
        for (int k = 0; k < 16; k++) reg[k] = psi[16 * k + t];

        fft256<true>(reg, t, buf + ly * 272, wf);
#pragma unroll
        for (int j = 0; j < 16; j++) reg[j] = cmul(reg[j], oc[16 * j + t]);
        fft256<false>(reg, t, buf + ly * 272, wf);

#pragma unroll
        for (int k = 0; k < 16; k++) psi[16 * k + t] = reg[k];
    }
}

// ---------------------------------------------------------------------------
// k_final: per column: Fc, accumulate |.|^2 over 4 probe modes, write dp.
// ---------------------------------------------------------------------------
__global__ __launch_bounds__(256, 2) void k_final(float* __restrict__ out) {
    __shared__ float2 buf[LNS * 272];
    int t = threadIdx.x, ly = threadIdx.y;
    int b = blockIdx.y;
    int cb = blockIdx.x * LNS;

    float2 wf = w256_fwd(t);
    float acc[16];
#pragma unroll
    for (int k = 0; k < 16; k++) acc[k] = 0.f;

    for (int pm = 0; pm < PM; pm++) {
        float2* psi = g_psi + (size_t)(b * PM + pm) * NN * NN;
#pragma unroll
        for (int it = 0; it < 16; it++) {
            int row = it * 16 + ly;
            buf[row * 17 + t] = psi[row * NN + cb + t];
        }
        __syncthreads();
        float2 reg[16];
#pragma unroll
        for (int j = 0; j < 16; j++) reg[j] = buf[(16 * j + t) * 17 + ly];
        __syncthreads();

        fft256<false>(reg, t, buf + ly * 272, wf);
#pragma unroll
        for (int k = 0; k < 16; k++)
            acc[k] = fmaf(reg[k].x, reg[k].x, fmaf(reg[k].y, reg[k].y, acc[k]));
        __syncthreads();  // buf reuse next pm (cross-line staging)
    }

    float* bf = (float*)buf;
#pragma unroll
    for (int k = 0; k < 16; k++) bf[(16 * k + t) * 17 + ly] = acc[k];
    __syncthreads();
#pragma unroll
    for (int it = 0; it < 16; it++) {
        int row = it * 16 + ly;
        out[(size_t)b * NN * NN + row * NN + cb + t] = bf[row * 17 + t];
    }
}

// ---------------------------------------------------------------------------
extern "C" void kernel_launch(void* const* d_in, const int* in_sizes, int n_in,
                              void* d_out, int out_size) {
    const float* obj    = (const float*)d_in[0];  // (1,8,1024,1024,2)
    const float* probe  = (const float*)d_in[1];  // (4,256,256,2)
    const float* shifts = (const float*)d_in[2];  // (1024,2)
    const int*   crop   = (const int*)d_in[3];    // (1024,2)
    const float* Hr     = (const float*)d_in[4];  // (256,256)
    const float* Hi     = (const float*)d_in[5];  // (256,256)
    const int*   idxs   = (const int*)d_in[6];    // (32,)
    float* out = (float*)d_out;                   // (32,256,256)

    k_prep<<<256, 256>>>(Hr, Hi);
    k_init<<<dim3(NN / LNS, NB * PM), dim3(16, LNS)>>>(obj, probe, shifts, crop, idxs);
    for (int z = 0; z < NSL - 1; z++) {
        k_col<<<dim3(NN / LNS, NB * PM), dim3(16, LNS)>>>();
        k_row<<<dim3(NN / LNSR, NB), dim3(16, LNSR)>>>(obj, crop, idxs, z + 1);
    }
    k_final<<<dim3(NN / LNS, NB), dim3(16, LNS)>>>(out);
}